// round 1
// baseline (speedup 1.0000x reference)
#include <cuda_runtime.h>
#include <math.h>

#define B_    4096
#define T_    24
#define NN    7
#define DYNV  6
#define INV   11
#define H     64
#define FUT   48
#define G     256

#define NB    4              // batch elems per block
#define ROWS  28             // NB * NN
#define BT    256            // threads per block
#define HS    68             // padded row stride for H=64 buffers
#define GS    260            // padded row stride for gate buffer

// Pre-transposed LSTM weights: [k][c] layout (k<64, c<256)
__device__ float g_wihT[H * G];
__device__ float g_whhT[H * G];

struct __align__(16) Smem {
    float xt[ROWS][12];
    float A[ROWS][HS];
    float Bv[ROWS][HS];
    float hx[ROWS][HS];
    float cx[ROWS][HS];
    float g[ROWS][GS];
    float adjn[NB][49];
    float deg[NB][8];
    float pred[ROWS][DYNV];
    float stat[ROWS][8];
};

__global__ void transpose_k(const float* __restrict__ w_ih,
                            const float* __restrict__ w_hh) {
    int i = blockIdx.x * blockDim.x + threadIdx.x;
    if (i < H * G) {
        int c = i / H, k = i - c * H;       // source: w[c][k], c<256, k<64
        g_wihT[k * G + c] = w_ih[i];
        g_whhT[k * G + c] = w_hh[i];
    }
}

__device__ __forceinline__ float sigm(float x) { return 1.0f / (1.0f + __expf(-x)); }

// out[r][c] = sum_k in[r][k] * W[k][c]   (ROWS x 64) @ (64 x 64), no bias/act
__device__ __forceinline__ void gemm64(const float (*in)[HS],
                                       const float* __restrict__ W,
                                       float (*out)[HS], int tid) {
    for (int idx = tid; idx < ROWS * 16; idx += BT) {
        int r = idx >> 4, c4 = (idx & 15) << 2;
        float4 acc = make_float4(0.f, 0.f, 0.f, 0.f);
        #pragma unroll
        for (int k = 0; k < H; k += 4) {
            float4 av = *reinterpret_cast<const float4*>(&in[r][k]);
            const float* ap = reinterpret_cast<const float*>(&av);
            #pragma unroll
            for (int j = 0; j < 4; j++) {
                float4 w = __ldg(reinterpret_cast<const float4*>(&W[(k + j) * H + c4]));
                acc.x = fmaf(ap[j], w.x, acc.x);
                acc.y = fmaf(ap[j], w.y, acc.y);
                acc.z = fmaf(ap[j], w.z, acc.z);
                acc.w = fmaf(ap[j], w.w, acc.w);
            }
        }
        *reinterpret_cast<float4*>(&out[r][c4]) = acc;
    }
}

// out[(b,i)][c] = relu( sum_j adjn[b][i][j] * in[(b,j)][c] + bias[c] )
__device__ __forceinline__ void mixadj(Smem* s, const float (*in)[HS],
                                       float (*out)[HS],
                                       const float* __restrict__ bias, int tid) {
    for (int idx = tid; idx < ROWS * 16; idx += BT) {
        int r = idx >> 4, c4 = (idx & 15) << 2;
        int b = r / 7, i = r - b * 7;
        float4 acc = __ldg(reinterpret_cast<const float4*>(&bias[c4]));
        #pragma unroll
        for (int j = 0; j < 7; j++) {
            float a = s->adjn[b][i * 7 + j];
            float4 v = *reinterpret_cast<const float4*>(&in[b * 7 + j][c4]);
            acc.x = fmaf(a, v.x, acc.x);
            acc.y = fmaf(a, v.y, acc.y);
            acc.z = fmaf(a, v.z, acc.z);
            acc.w = fmaf(a, v.w, acc.w);
        }
        acc.x = fmaxf(acc.x, 0.f);
        acc.y = fmaxf(acc.y, 0.f);
        acc.z = fmaxf(acc.z, 0.f);
        acc.w = fmaxf(acc.w, 0.f);
        *reinterpret_cast<float4*>(&out[r][c4]) = acc;
    }
}

// g[r][c] = A[r]·wihT[:,c] + hx[r]·whhT[:,c] + b_ih[c] + b_hh[c]
// Thread tile: 7 rows x 4 cols. tid&63 -> col tile, tid>>6 -> row tile.
__device__ __forceinline__ void lstm_gemm(Smem* s, int tid,
                                          const float* __restrict__ b_ih,
                                          const float* __restrict__ b_hh) {
    const int c4 = (tid & 63) << 2;
    const int r0 = (tid >> 6) * 7;
    float4 acc[7];
    #pragma unroll
    for (int i = 0; i < 7; i++) acc[i] = make_float4(0.f, 0.f, 0.f, 0.f);

    #pragma unroll 4
    for (int k = 0; k < H; k += 4) {
        float4 a[7];
        #pragma unroll
        for (int i = 0; i < 7; i++)
            a[i] = *reinterpret_cast<const float4*>(&s->A[r0 + i][k]);
        #pragma unroll
        for (int j = 0; j < 4; j++) {
            float4 w = __ldg(reinterpret_cast<const float4*>(&g_wihT[(k + j) * G + c4]));
            #pragma unroll
            for (int i = 0; i < 7; i++) {
                const float* ap = reinterpret_cast<const float*>(&a[i]);
                float aa = ap[j];
                acc[i].x = fmaf(aa, w.x, acc[i].x);
                acc[i].y = fmaf(aa, w.y, acc[i].y);
                acc[i].z = fmaf(aa, w.z, acc[i].z);
                acc[i].w = fmaf(aa, w.w, acc[i].w);
            }
        }
    }
    #pragma unroll 4
    for (int k = 0; k < H; k += 4) {
        float4 a[7];
        #pragma unroll
        for (int i = 0; i < 7; i++)
            a[i] = *reinterpret_cast<const float4*>(&s->hx[r0 + i][k]);
        #pragma unroll
        for (int j = 0; j < 4; j++) {
            float4 w = __ldg(reinterpret_cast<const float4*>(&g_whhT[(k + j) * G + c4]));
            #pragma unroll
            for (int i = 0; i < 7; i++) {
                const float* ap = reinterpret_cast<const float*>(&a[i]);
                float aa = ap[j];
                acc[i].x = fmaf(aa, w.x, acc[i].x);
                acc[i].y = fmaf(aa, w.y, acc[i].y);
                acc[i].z = fmaf(aa, w.z, acc[i].z);
                acc[i].w = fmaf(aa, w.w, acc[i].w);
            }
        }
    }
    float4 bi = __ldg(reinterpret_cast<const float4*>(&b_ih[c4]));
    float4 bh = __ldg(reinterpret_cast<const float4*>(&b_hh[c4]));
    #pragma unroll
    for (int i = 0; i < 7; i++) {
        float4 o = acc[i];
        o.x += bi.x + bh.x;
        o.y += bi.y + bh.y;
        o.z += bi.z + bh.z;
        o.w += bi.w + bh.w;
        *reinterpret_cast<float4*>(&s->g[r0 + i][c4]) = o;
    }
}

// One LSTM cell step. Expects s->xt filled + synced. Leaves hx/cx updated + synced.
__device__ __forceinline__ void cell(Smem* s, int tid,
        const float* __restrict__ enc_w, const float* __restrict__ enc_b,
        const float* __restrict__ g1w,   const float* __restrict__ g1b,
        const float* __restrict__ g2w,   const float* __restrict__ g2b,
        const float* __restrict__ b_ih,  const float* __restrict__ b_hh) {
    // encoder: A = relu(xt @ enc_w + enc_b)
    for (int idx = tid; idx < ROWS * H; idx += BT) {
        int r = idx >> 6, c = idx & 63;
        float acc = __ldg(&enc_b[c]);
        #pragma unroll
        for (int k = 0; k < INV; k++)
            acc = fmaf(s->xt[r][k], __ldg(&enc_w[k * H + c]), acc);
        s->A[r][c] = fmaxf(acc, 0.f);
    }
    __syncthreads();
    gemm64(s->A, g1w, s->Bv, tid);
    __syncthreads();
    mixadj(s, s->Bv, s->A, g1b, tid);
    __syncthreads();
    gemm64(s->A, g2w, s->Bv, tid);
    __syncthreads();
    mixadj(s, s->Bv, s->A, g2b, tid);
    __syncthreads();
    lstm_gemm(s, tid, b_ih, b_hh);
    __syncthreads();
    // gates
    for (int idx = tid; idx < ROWS * H; idx += BT) {
        int r = idx >> 6, h = idx & 63;
        float ig = sigm(s->g[r][h]);
        float fg = sigm(s->g[r][h + 64]);
        float gg = tanhf(s->g[r][h + 128]);
        float og = sigm(s->g[r][h + 192]);
        float c = fg * s->cx[r][h] + ig * gg;
        s->cx[r][h] = c;
        s->hx[r][h] = og * tanhf(c);
    }
    __syncthreads();
}

__global__ void __launch_bounds__(BT)
stgnn_kernel(const float* __restrict__ xh,    const float* __restrict__ adj,
             const float* __restrict__ enc_w, const float* __restrict__ enc_b,
             const float* __restrict__ g1w,   const float* __restrict__ g1b,
             const float* __restrict__ g2w,   const float* __restrict__ g2b,
             const float* __restrict__ b_ih,  const float* __restrict__ b_hh,
             const float* __restrict__ d1w,   const float* __restrict__ d1b,
             const float* __restrict__ d2w,   const float* __restrict__ d2b,
             float* __restrict__ out) {
    extern __shared__ Smem sm[];
    Smem* s = sm;
    const int tid = threadIdx.x;
    const int b0 = blockIdx.x * NB;

    // ---- normalized adjacency (per batch elem), hx/cx = 0 ----
    for (int idx = tid; idx < NB * 49; idx += BT) {
        int b = idx / 49, ij = idx - b * 49;
        int i = ij / 7, j = ij - i * 7;
        float v = (i == j) ? 1.0f : __ldg(&adj[(b0 + b) * 49 + ij]);
        s->adjn[b][ij] = v;
    }
    for (int idx = tid; idx < ROWS * H; idx += BT) {
        int r = idx >> 6, c = idx & 63;
        s->hx[r][c] = 0.f;
        s->cx[r][c] = 0.f;
    }
    __syncthreads();
    if (tid < NB * 7) {
        int b = tid / 7, i = tid - b * 7;
        float sum = 0.f;
        #pragma unroll
        for (int j = 0; j < 7; j++) sum += s->adjn[b][i * 7 + j];
        s->deg[b][i] = rsqrtf(fmaxf(sum, 1.0f));
    }
    __syncthreads();
    for (int idx = tid; idx < NB * 49; idx += BT) {
        int b = idx / 49, ij = idx - b * 49;
        int i = ij / 7, j = ij - i * 7;
        s->adjn[b][ij] *= s->deg[b][i] * s->deg[b][j];
    }
    __syncthreads();

    // ---- history scan ----
    #pragma unroll 1
    for (int t = 0; t < T_; t++) {
        for (int idx = tid; idx < ROWS * INV; idx += BT) {
            int r = idx / INV, k = idx - r * INV;
            int b = b0 + r / 7, n = r - (r / 7) * 7;
            s->xt[r][k] = __ldg(&xh[((b * T_ + t) * NN + n) * INV + k]);
        }
        __syncthreads();
        cell(s, tid, enc_w, enc_b, g1w, g1b, g2w, g2b, b_ih, b_hh);
    }

    // ---- pred/stat init from last history step ----
    for (int idx = tid; idx < ROWS * INV; idx += BT) {
        int r = idx / INV, k = idx - r * INV;
        int b = b0 + r / 7, n = r - (r / 7) * 7;
        float v = __ldg(&xh[((b * T_ + (T_ - 1)) * NN + n) * INV + k]);
        if (k < DYNV) s->pred[r][k] = v;
        else          s->stat[r][k - DYNV] = v;
    }
    __syncthreads();

    // ---- future rollout ----
    #pragma unroll 1
    for (int f = 0; f < FUT; f++) {
        for (int idx = tid; idx < ROWS * INV; idx += BT) {
            int r = idx / INV, k = idx - r * INV;
            s->xt[r][k] = (k < DYNV) ? s->pred[r][k] : s->stat[r][k - DYNV];
        }
        __syncthreads();
        cell(s, tid, enc_w, enc_b, g1w, g1b, g2w, g2b, b_ih, b_hh);

        // decoder layer 1: A = relu(hx @ d1w + d1b)   (ROWS x 32)
        for (int idx = tid; idx < ROWS * 8; idx += BT) {
            int r = idx >> 3, c4 = (idx & 7) << 2;
            float4 acc = __ldg(reinterpret_cast<const float4*>(&d1b[c4]));
            #pragma unroll
            for (int k = 0; k < H; k += 4) {
                float4 av = *reinterpret_cast<const float4*>(&s->hx[r][k]);
                const float* ap = reinterpret_cast<const float*>(&av);
                #pragma unroll
                for (int j = 0; j < 4; j++) {
                    float4 w = __ldg(reinterpret_cast<const float4*>(&d1w[(k + j) * 32 + c4]));
                    acc.x = fmaf(ap[j], w.x, acc.x);
                    acc.y = fmaf(ap[j], w.y, acc.y);
                    acc.z = fmaf(ap[j], w.z, acc.z);
                    acc.w = fmaf(ap[j], w.w, acc.w);
                }
            }
            acc.x = fmaxf(acc.x, 0.f);
            acc.y = fmaxf(acc.y, 0.f);
            acc.z = fmaxf(acc.z, 0.f);
            acc.w = fmaxf(acc.w, 0.f);
            *reinterpret_cast<float4*>(&s->A[r][c4]) = acc;
        }
        __syncthreads();

        // decoder layer 2 + residual + clip + output write
        for (int idx = tid; idx < ROWS * DYNV; idx += BT) {
            int r = idx / DYNV, d = idx - r * DYNV;
            float acc = __ldg(&d2b[d]);
            #pragma unroll
            for (int j = 0; j < 32; j++)
                acc = fmaf(s->A[r][j], __ldg(&d2w[j * DYNV + d]), acc);
            float res = tanhf(acc) * 0.05f;
            float p = s->pred[r][d] + res;
            p = fminf(fmaxf(p, 0.f), 1.f);
            s->pred[r][d] = p;
            int b = b0 + r / 7, n = r - (r / 7) * 7;
            out[((b * FUT + f) * NN + n) * DYNV + d] = p;
        }
        __syncthreads();
    }
}

extern "C" void kernel_launch(void* const* d_in, const int* in_sizes, int n_in,
                              void* d_out, int out_size) {
    const float* xh    = (const float*)d_in[0];
    const float* adj   = (const float*)d_in[1];
    const float* enc_w = (const float*)d_in[2];
    const float* enc_b = (const float*)d_in[3];
    const float* g1w   = (const float*)d_in[4];
    const float* g1b   = (const float*)d_in[5];
    const float* g2w   = (const float*)d_in[6];
    const float* g2b   = (const float*)d_in[7];
    const float* w_ih  = (const float*)d_in[8];
    const float* w_hh  = (const float*)d_in[9];
    const float* b_ih  = (const float*)d_in[10];
    const float* b_hh  = (const float*)d_in[11];
    const float* d1w   = (const float*)d_in[12];
    const float* d1b   = (const float*)d_in[13];
    const float* d2w   = (const float*)d_in[14];
    const float* d2b   = (const float*)d_in[15];
    float* out = (float*)d_out;

    cudaFuncSetAttribute(stgnn_kernel, cudaFuncAttributeMaxDynamicSharedMemorySize,
                         (int)sizeof(Smem));

    transpose_k<<<(H * G + 255) / 256, 256>>>(w_ih, w_hh);
    stgnn_kernel<<<B_ / NB, BT, sizeof(Smem)>>>(
        xh, adj, enc_w, enc_b, g1w, g1b, g2w, g2b,
        b_ih, b_hh, d1w, d1b, d2w, d2b, out);
}

// round 2
// speedup vs baseline: 1.5641x; 1.5641x over previous
#include <cuda_runtime.h>
#include <math.h>

#define B_    4096
#define T_    24
#define NN    7
#define DYNV  6
#define INV   11
#define H     64
#define FUT   48
#define G     256

#define NB    4              // batch elems per block
#define ROWS  28             // NB * NN
#define BT    256            // threads per block
#define HS    68             // padded row stride for H=64 buffers

typedef unsigned long long ull;

// Packed-k weight layouts: pairs (w[2kp][c], w[2kp+1][c]) adjacent.
__device__ float g_wih2[32 * 256 * 2];   // [kp][gatecol][2], from w_ih (256,64): pair = w_ih[c][2kp+p]
__device__ float g_whh2[32 * 256 * 2];
__device__ float g_g1w2[32 * 64 * 2];    // [kp][c][2] from g1w (64,64)
__device__ float g_g2w2[32 * 64 * 2];
__device__ float g_enc2[6 * 64 * 2];     // k padded 11 -> 12
__device__ float g_d1w2[32 * 32 * 2];
__device__ float g_d2w2[16 * 6 * 2];

struct __align__(16) Smem {
    float xt[ROWS][12];      // k=11 slot zeroed
    float A[ROWS][HS];
    float Bv[ROWS][HS];
    float hx[ROWS][HS];
    float cx[ROWS][HS];
    float adjn[NB][49];
    float deg[NB][8];
    float pred[ROWS][DYNV];
    float stat[ROWS][8];
};

__global__ void pack_weights(const float* __restrict__ w_ih, const float* __restrict__ w_hh,
                             const float* __restrict__ g1w,  const float* __restrict__ g2w,
                             const float* __restrict__ enc_w,
                             const float* __restrict__ d1w,  const float* __restrict__ d2w) {
    int i = blockIdx.x * blockDim.x + threadIdx.x;
    if (i < 16384) {
        int p = i & 1, c = (i >> 1) & 255, kp = i >> 9;
        g_wih2[i] = w_ih[c * 64 + 2 * kp + p];
        g_whh2[i] = w_hh[c * 64 + 2 * kp + p];
    } else if (i < 16384 + 4096) {
        int j = i - 16384;
        int p = j & 1, c = (j >> 1) & 63, kp = j >> 7;
        g_g1w2[j] = g1w[(2 * kp + p) * 64 + c];
        g_g2w2[j] = g2w[(2 * kp + p) * 64 + c];
    } else if (i < 16384 + 4096 + 768) {
        int j = i - 16384 - 4096;
        int p = j & 1, c = (j >> 1) & 63, kp = j >> 7;
        int k = 2 * kp + p;
        g_enc2[j] = (k < INV) ? enc_w[k * 64 + c] : 0.f;
    } else if (i < 16384 + 4096 + 768 + 2048) {
        int j = i - 16384 - 4096 - 768;
        int p = j & 1, c = (j >> 1) & 31, kp = j >> 6;
        g_d1w2[j] = d1w[(2 * kp + p) * 32 + c];
    } else if (i < 16384 + 4096 + 768 + 2048 + 192) {
        int j = i - (16384 + 4096 + 768 + 2048);
        int kp = j / 12, r = j - kp * 12, d = r >> 1, p = r & 1;
        g_d2w2[j] = d2w[(2 * kp + p) * 6 + d];
    }
}

// ---------- packed f32x2 helpers ----------
__device__ __forceinline__ ull ldsm2(const float* p) {
    return *reinterpret_cast<const ull*>(p);
}
__device__ __forceinline__ ull ldg2(const float* p) {
    return __ldg(reinterpret_cast<const ull*>(p));
}
__device__ __forceinline__ void ffma2(ull& d, ull a, ull b) {
    asm("fma.rn.f32x2 %0, %1, %2, %3;" : "=l"(d) : "l"(a), "l"(b), "l"(d));
}
__device__ __forceinline__ ull pack2(float x, float y) {
    ull r;
    asm("mov.b64 %0, {%1, %2};" : "=l"(r) : "f"(x), "f"(y));
    return r;
}
__device__ __forceinline__ float hsum(ull v) {
    float2 f = *reinterpret_cast<float2*>(&v);
    return f.x + f.y;
}
__device__ __forceinline__ float sigm_f(float x) {
    return __fdividef(1.f, 1.f + __expf(-x));
}
__device__ __forceinline__ float tanh_f(float x) {
    float e = __expf(2.f * x);
    return 1.f - __fdividef(2.f, e + 1.f);
}

// out[r][c] = sum_k in[r][k] * W[k][c], packed-k; 128 active threads, tile 7r x 2c.
__device__ __forceinline__ void gemm64_p(const float (*in)[HS],
                                         const float* __restrict__ w2,
                                         float (*out)[HS], int tid) {
    if (tid < 128) {
        int rg = tid >> 5, cp = tid & 31;
        int r0 = rg * 7, c0 = cp * 2;
        ull acc0[7] = {}, acc1[7] = {};
        #pragma unroll 4
        for (int kp = 0; kp < 32; kp++) {
            ulonglong2 w = __ldg(reinterpret_cast<const ulonglong2*>(&w2[(kp * 64 + c0) * 2]));
            #pragma unroll
            for (int i = 0; i < 7; i++) {
                ull a = ldsm2(&in[r0 + i][2 * kp]);
                ffma2(acc0[i], a, w.x);
                ffma2(acc1[i], a, w.y);
            }
        }
        #pragma unroll
        for (int i = 0; i < 7; i++)
            *reinterpret_cast<float2*>(&out[r0 + i][c0]) =
                make_float2(hsum(acc0[i]), hsum(acc1[i]));
    }
}

// out = relu(adjn @ in + bias)
__device__ __forceinline__ void mixadj_p(Smem* s, const float (*in)[HS],
                                         float (*out)[HS],
                                         const float* __restrict__ bias, int tid) {
    for (int idx = tid; idx < ROWS * 16; idx += BT) {
        int r = idx >> 4, c4 = (idx & 15) << 2;
        int b = r / 7, i = r - b * 7;
        float4 bv = __ldg(reinterpret_cast<const float4*>(&bias[c4]));
        ull acc0 = pack2(bv.x, bv.y), acc1 = pack2(bv.z, bv.w);
        #pragma unroll
        for (int j = 0; j < 7; j++) {
            float a = s->adjn[b][i * 7 + j];
            ull a2 = pack2(a, a);
            ulonglong2 v = *reinterpret_cast<const ulonglong2*>(&in[b * 7 + j][c4]);
            ffma2(acc0, a2, v.x);
            ffma2(acc1, a2, v.y);
        }
        float2 f0 = *reinterpret_cast<float2*>(&acc0);
        float2 f1 = *reinterpret_cast<float2*>(&acc1);
        float4 o = make_float4(fmaxf(f0.x, 0.f), fmaxf(f0.y, 0.f),
                               fmaxf(f1.x, 0.f), fmaxf(f1.y, 0.f));
        *reinterpret_cast<float4*>(&out[r][c4]) = o;
    }
}

// One cell step: xt must be filled+synced. Updates hx/cx, synced on exit.
__device__ __forceinline__ void cell(Smem* s, int tid,
        const float* __restrict__ enc_b,
        const float* __restrict__ g1b, const float* __restrict__ g2b,
        const float* __restrict__ b_ih, const float* __restrict__ b_hh) {
    // ---- encoder: A = relu(xt @ enc_w + enc_b), packed-k (6 kp), 128 threads ----
    if (tid < 128) {
        int rg = tid >> 5, cp = tid & 31;
        int r0 = rg * 7, c0 = cp * 2;
        ull acc0[7] = {}, acc1[7] = {};
        #pragma unroll
        for (int kp = 0; kp < 6; kp++) {
            ulonglong2 w = __ldg(reinterpret_cast<const ulonglong2*>(&g_enc2[(kp * 64 + c0) * 2]));
            #pragma unroll
            for (int i = 0; i < 7; i++) {
                ull a = ldsm2(&s->xt[r0 + i][2 * kp]);
                ffma2(acc0[i], a, w.x);
                ffma2(acc1[i], a, w.y);
            }
        }
        float b0 = __ldg(&enc_b[c0]), b1 = __ldg(&enc_b[c0 + 1]);
        #pragma unroll
        for (int i = 0; i < 7; i++)
            *reinterpret_cast<float2*>(&s->A[r0 + i][c0]) =
                make_float2(fmaxf(hsum(acc0[i]) + b0, 0.f),
                            fmaxf(hsum(acc1[i]) + b1, 0.f));
    }
    __syncthreads();
    gemm64_p(s->A, g_g1w2, s->Bv, tid);
    __syncthreads();
    mixadj_p(s, s->Bv, s->A, g1b, tid);
    __syncthreads();
    gemm64_p(s->A, g_g2w2, s->Bv, tid);
    __syncthreads();
    mixadj_p(s, s->Bv, s->A, g2b, tid);
    __syncthreads();

    // ---- LSTM gates fused: each thread owns cols {h, h+64, h+128, h+192} for 7 rows ----
    {
        int cg = tid & 63, rg = tid >> 6, r0 = rg * 7;
        ull acc[4][7] = {};
        #pragma unroll 2
        for (int kp = 0; kp < 32; kp++) {
            ull aA[7], aH[7];
            #pragma unroll
            for (int i = 0; i < 7; i++) {
                aA[i] = ldsm2(&s->A[r0 + i][2 * kp]);
                aH[i] = ldsm2(&s->hx[r0 + i][2 * kp]);
            }
            #pragma unroll
            for (int g = 0; g < 4; g++) {
                ull wi = ldg2(&g_wih2[(kp * 256 + g * 64 + cg) * 2]);
                ull wh = ldg2(&g_whh2[(kp * 256 + g * 64 + cg) * 2]);
                #pragma unroll
                for (int i = 0; i < 7; i++) {
                    ffma2(acc[g][i], aA[i], wi);
                    ffma2(acc[g][i], aH[i], wh);
                }
            }
        }
        float bi = __ldg(&b_ih[cg])       + __ldg(&b_hh[cg]);
        float bf = __ldg(&b_ih[64 + cg])  + __ldg(&b_hh[64 + cg]);
        float bg = __ldg(&b_ih[128 + cg]) + __ldg(&b_hh[128 + cg]);
        float bo = __ldg(&b_ih[192 + cg]) + __ldg(&b_hh[192 + cg]);
        __syncthreads();   // all hx reads done before overwrite
        #pragma unroll
        for (int i = 0; i < 7; i++) {
            float gi = sigm_f(hsum(acc[0][i]) + bi);
            float gf = sigm_f(hsum(acc[1][i]) + bf);
            float gg = tanh_f(hsum(acc[2][i]) + bg);
            float go = sigm_f(hsum(acc[3][i]) + bo);
            float c  = gf * s->cx[r0 + i][cg] + gi * gg;
            s->cx[r0 + i][cg] = c;
            s->hx[r0 + i][cg] = go * tanh_f(c);
        }
    }
    __syncthreads();
}

__global__ void __launch_bounds__(BT, 2)
stgnn_kernel(const float* __restrict__ xh,    const float* __restrict__ adj,
             const float* __restrict__ enc_b,
             const float* __restrict__ g1b,   const float* __restrict__ g2b,
             const float* __restrict__ b_ih,  const float* __restrict__ b_hh,
             const float* __restrict__ d1b,   const float* __restrict__ d2b,
             float* __restrict__ out) {
    __shared__ Smem sm;
    Smem* s = &sm;
    const int tid = threadIdx.x;
    const int b0 = blockIdx.x * NB;

    // ---- normalized adjacency + zero state ----
    for (int idx = tid; idx < NB * 49; idx += BT) {
        int b = idx / 49, ij = idx - b * 49;
        int i = ij / 7, j = ij - i * 7;
        s->adjn[b][ij] = (i == j) ? 1.0f : __ldg(&adj[(b0 + b) * 49 + ij]);
    }
    for (int idx = tid; idx < ROWS * H; idx += BT) {
        int r = idx >> 6, c = idx & 63;
        s->hx[r][c] = 0.f;
        s->cx[r][c] = 0.f;
    }
    __syncthreads();
    if (tid < NB * 7) {
        int b = tid / 7, i = tid - b * 7;
        float sum = 0.f;
        #pragma unroll
        for (int j = 0; j < 7; j++) sum += s->adjn[b][i * 7 + j];
        s->deg[b][i] = rsqrtf(fmaxf(sum, 1.0f));
    }
    __syncthreads();
    for (int idx = tid; idx < NB * 49; idx += BT) {
        int b = idx / 49, ij = idx - b * 49;
        int i = ij / 7, j = ij - i * 7;
        s->adjn[b][ij] *= s->deg[b][i] * s->deg[b][j];
    }
    __syncthreads();

    // ---- history scan ----
    #pragma unroll 1
    for (int t = 0; t < T_; t++) {
        for (int idx = tid; idx < ROWS * 12; idx += BT) {
            int r = idx / 12, k = idx - r * 12;
            int bb = r / 7, n = r - bb * 7;
            float v = 0.f;
            if (k < INV) v = __ldg(&xh[(((b0 + bb) * T_ + t) * NN + n) * INV + k]);
            s->xt[r][k] = v;
        }
        __syncthreads();
        cell(s, tid, enc_b, g1b, g2b, b_ih, b_hh);
    }

    // ---- pred/stat init from last history step ----
    for (int idx = tid; idx < ROWS * INV; idx += BT) {
        int r = idx / INV, k = idx - r * INV;
        int bb = r / 7, n = r - bb * 7;
        float v = __ldg(&xh[(((b0 + bb) * T_ + (T_ - 1)) * NN + n) * INV + k]);
        if (k < DYNV) s->pred[r][k] = v;
        else          s->stat[r][k - DYNV] = v;
    }
    __syncthreads();

    // ---- future rollout ----
    #pragma unroll 1
    for (int f = 0; f < FUT; f++) {
        for (int idx = tid; idx < ROWS * 12; idx += BT) {
            int r = idx / 12, k = idx - r * 12;
            float v = 0.f;
            if (k < DYNV)      v = s->pred[r][k];
            else if (k < INV)  v = s->stat[r][k - DYNV];
            s->xt[r][k] = v;
        }
        __syncthreads();
        cell(s, tid, enc_b, g1b, g2b, b_ih, b_hh);

        // decoder layer 1: A[:, :32] = relu(hx @ d1w + d1b), 64 threads
        if (tid < 64) {
            int rg = tid >> 4, cp = tid & 15;
            int r0 = rg * 7, c0 = cp * 2;
            ull acc0[7] = {}, acc1[7] = {};
            #pragma unroll 4
            for (int kp = 0; kp < 32; kp++) {
                ulonglong2 w = __ldg(reinterpret_cast<const ulonglong2*>(&g_d1w2[(kp * 32 + c0) * 2]));
                #pragma unroll
                for (int i = 0; i < 7; i++) {
                    ull a = ldsm2(&s->hx[r0 + i][2 * kp]);
                    ffma2(acc0[i], a, w.x);
                    ffma2(acc1[i], a, w.y);
                }
            }
            float bb0 = __ldg(&d1b[c0]), bb1 = __ldg(&d1b[c0 + 1]);
            #pragma unroll
            for (int i = 0; i < 7; i++)
                *reinterpret_cast<float2*>(&s->A[r0 + i][c0]) =
                    make_float2(fmaxf(hsum(acc0[i]) + bb0, 0.f),
                                fmaxf(hsum(acc1[i]) + bb1, 0.f));
        }
        __syncthreads();

        // decoder layer 2 + residual + clip + output
        if (tid < ROWS * DYNV) {
            int r = tid / DYNV, d = tid - r * DYNV;
            ull acc = pack2(0.f, 0.f);
            #pragma unroll
            for (int kp = 0; kp < 16; kp++) {
                ull a = ldsm2(&s->A[r][2 * kp]);
                ull w = ldg2(&g_d2w2[(kp * 6 + d) * 2]);
                ffma2(acc, a, w);
            }
            float res = tanh_f(hsum(acc) + __ldg(&d2b[d])) * 0.05f;
            float p = fminf(fmaxf(s->pred[r][d] + res, 0.f), 1.f);
            s->pred[r][d] = p;
            int bb = b0 + r / 7, n = r - (r / 7) * 7;
            out[((bb * FUT + f) * NN + n) * DYNV + d] = p;
        }
        __syncthreads();
    }
}

extern "C" void kernel_launch(void* const* d_in, const int* in_sizes, int n_in,
                              void* d_out, int out_size) {
    const float* xh    = (const float*)d_in[0];
    const float* adj   = (const float*)d_in[1];
    const float* enc_w = (const float*)d_in[2];
    const float* enc_b = (const float*)d_in[3];
    const float* g1w   = (const float*)d_in[4];
    const float* g1b   = (const float*)d_in[5];
    const float* g2w   = (const float*)d_in[6];
    const float* g2b   = (const float*)d_in[7];
    const float* w_ih  = (const float*)d_in[8];
    const float* w_hh  = (const float*)d_in[9];
    const float* b_ih  = (const float*)d_in[10];
    const float* b_hh  = (const float*)d_in[11];
    const float* d1w   = (const float*)d_in[12];
    const float* d1b   = (const float*)d_in[13];
    const float* d2w   = (const float*)d_in[14];
    const float* d2b   = (const float*)d_in[15];
    float* out = (float*)d_out;

    pack_weights<<<(23488 + 255) / 256, 256>>>(w_ih, w_hh, g1w, g2w, enc_w, d1w, d2w);
    stgnn_kernel<<<B_ / NB, BT>>>(xh, adj, enc_b, g1b, g2b, b_ih, b_hh, d1b, d2b, out);
}

// round 3
// speedup vs baseline: 1.5689x; 1.0031x over previous
#include <cuda_runtime.h>
#include <math.h>

#define B_    4096
#define T_    24
#define NN    7
#define DYNV  6
#define INV   11
#define H     64
#define FUT   48

#define BT    64            // threads per block (one batch element per block)
#define HS    68            // padded row stride

typedef unsigned long long ull;

// Packed-k weight layouts: pairs (w[2kp][c], w[2kp+1][c]) adjacent.
__device__ float g_wih2[32 * 256 * 2];   // [kp][gatecol][2] from w_ih (256,64)
__device__ float g_whh2[32 * 256 * 2];
__device__ float g_g1w2[32 * 64 * 2];
__device__ float g_g2w2[32 * 64 * 2];
__device__ float g_enc2[6 * 64 * 2];     // k padded 11 -> 12
__device__ float g_d1w2[32 * 32 * 2];
__device__ float g_d2w2[16 * 6 * 2];

__global__ void pack_weights(const float* __restrict__ w_ih, const float* __restrict__ w_hh,
                             const float* __restrict__ g1w,  const float* __restrict__ g2w,
                             const float* __restrict__ enc_w,
                             const float* __restrict__ d1w,  const float* __restrict__ d2w) {
    int i = blockIdx.x * blockDim.x + threadIdx.x;
    if (i < 16384) {
        int p = i & 1, c = (i >> 1) & 255, kp = i >> 9;
        g_wih2[i] = w_ih[c * 64 + 2 * kp + p];
        g_whh2[i] = w_hh[c * 64 + 2 * kp + p];
    } else if (i < 16384 + 4096) {
        int j = i - 16384;
        int p = j & 1, c = (j >> 1) & 63, kp = j >> 7;
        g_g1w2[j] = g1w[(2 * kp + p) * 64 + c];
        g_g2w2[j] = g2w[(2 * kp + p) * 64 + c];
    } else if (i < 16384 + 4096 + 768) {
        int j = i - 16384 - 4096;
        int p = j & 1, c = (j >> 1) & 63, kp = j >> 7;
        int k = 2 * kp + p;
        g_enc2[j] = (k < INV) ? enc_w[k * 64 + c] : 0.f;
    } else if (i < 16384 + 4096 + 768 + 2048) {
        int j = i - 16384 - 4096 - 768;
        int p = j & 1, c = (j >> 1) & 31, kp = j >> 6;
        g_d1w2[j] = d1w[(2 * kp + p) * 32 + c];
    } else if (i < 16384 + 4096 + 768 + 2048 + 192) {
        int j = i - (16384 + 4096 + 768 + 2048);
        int kp = j / 12, r = j - kp * 12, d = r >> 1, p = r & 1;
        g_d2w2[j] = d2w[(2 * kp + p) * 6 + d];
    }
}

// ---------- packed f32x2 helpers ----------
__device__ __forceinline__ ull ldsm2(const float* p) { return *reinterpret_cast<const ull*>(p); }
__device__ __forceinline__ ull ldg2(const float* p)  { return __ldg(reinterpret_cast<const ull*>(p)); }
__device__ __forceinline__ void ffma2(ull& d, ull a, ull b) {
    asm("fma.rn.f32x2 %0, %1, %2, %3;" : "=l"(d) : "l"(a), "l"(b), "l"(d));
}
__device__ __forceinline__ float hsum(ull v) {
    float2 f = *reinterpret_cast<float2*>(&v);
    return f.x + f.y;
}
__device__ __forceinline__ float sigm_f(float x) { return __fdividef(1.f, 1.f + __expf(-x)); }
__device__ __forceinline__ float tanh_f(float x) {
    float e = __expf(2.f * x);
    return 1.f - __fdividef(2.f, e + 1.f);
}

struct __align__(16) Smem {
    float xt[NN][12];        // k=11 slot zeroed
    float A[NN][HS];
    float Bv[NN][HS];
    float hx[NN][HS];
    float cx[NN][HS];
    float adjn[49];
    float deg[8];
    float pred[NN][DYNV];
    float stat[NN][8];
};

// (7 x 64) @ (64 x 64): thread c computes column c for all 7 rows. No bias/relu.
__device__ __forceinline__ void gemm64_p(const float (*in)[HS],
                                         const float* __restrict__ w2,
                                         float (*out)[HS], int c) {
    ull acc[NN] = {};
    #pragma unroll 4
    for (int kp = 0; kp < 32; kp++) {
        ull w = ldg2(&w2[(kp * 64 + c) * 2]);
        #pragma unroll
        for (int r = 0; r < NN; r++)
            ffma2(acc[r], ldsm2(&in[r][2 * kp]), w);
    }
    #pragma unroll
    for (int r = 0; r < NN; r++) out[r][c] = hsum(acc[r]);
}

// out[i][c] = relu( sum_j adjn[i][j]*in[j][c] + bias[c] )
__device__ __forceinline__ void mixadj_p(const Smem* s, const float (*in)[HS],
                                         float (*out)[HS],
                                         const float* __restrict__ bias, int c) {
    float v[NN];
    #pragma unroll
    for (int j = 0; j < NN; j++) v[j] = in[j][c];
    float bb = __ldg(&bias[c]);
    #pragma unroll
    for (int i = 0; i < NN; i++) {
        float acc = bb;
        #pragma unroll
        for (int j = 0; j < NN; j++)
            acc = fmaf(s->adjn[i * 7 + j], v[j], acc);
        out[i][c] = fmaxf(acc, 0.f);
    }
}

// One LSTM cell step. xt filled+synced on entry; hx/cx updated+synced on exit.
__device__ __forceinline__ void cell(Smem* s, int c,
        const float* __restrict__ enc_b,
        const float* __restrict__ g1b, const float* __restrict__ g2b,
        const float* __restrict__ b_ih, const float* __restrict__ b_hh) {
    // encoder: A = relu(xt @ enc_w + enc_b)
    {
        ull acc[NN] = {};
        #pragma unroll
        for (int kp = 0; kp < 6; kp++) {
            ull w = ldg2(&g_enc2[(kp * 64 + c) * 2]);
            #pragma unroll
            for (int r = 0; r < NN; r++)
                ffma2(acc[r], ldsm2(&s->xt[r][2 * kp]), w);
        }
        float bb = __ldg(&enc_b[c]);
        #pragma unroll
        for (int r = 0; r < NN; r++)
            s->A[r][c] = fmaxf(hsum(acc[r]) + bb, 0.f);
    }
    __syncthreads();
    gemm64_p(s->A, g_g1w2, s->Bv, c);
    __syncthreads();
    mixadj_p(s, s->Bv, s->A, g1b, c);
    __syncthreads();
    gemm64_p(s->A, g_g2w2, s->Bv, c);
    __syncthreads();
    mixadj_p(s, s->Bv, s->A, g2b, c);
    __syncthreads();

    // LSTM gates, 2 passes (i,g) then (f,o); thread c owns gate cols {c,c+64,c+128,c+192}.
    float ig[NN];   // sigm(i)*tanh(g) per row
    {
        ull a0[NN] = {}, a2[NN] = {};
        #pragma unroll 2
        for (int kp = 0; kp < 32; kp++) {
            ull wi0 = ldg2(&g_wih2[(kp * 256 + c) * 2]);
            ull wh0 = ldg2(&g_whh2[(kp * 256 + c) * 2]);
            ull wi2 = ldg2(&g_wih2[(kp * 256 + 128 + c) * 2]);
            ull wh2 = ldg2(&g_whh2[(kp * 256 + 128 + c) * 2]);
            #pragma unroll
            for (int r = 0; r < NN; r++) {
                ull aA = ldsm2(&s->A[r][2 * kp]);
                ull aH = ldsm2(&s->hx[r][2 * kp]);
                ffma2(a0[r], aA, wi0);
                ffma2(a0[r], aH, wh0);
                ffma2(a2[r], aA, wi2);
                ffma2(a2[r], aH, wh2);
            }
        }
        float bI = __ldg(&b_ih[c])       + __ldg(&b_hh[c]);
        float bG = __ldg(&b_ih[128 + c]) + __ldg(&b_hh[128 + c]);
        #pragma unroll
        for (int r = 0; r < NN; r++)
            ig[r] = sigm_f(hsum(a0[r]) + bI) * tanh_f(hsum(a2[r]) + bG);
    }
    {
        ull a1[NN] = {}, a3[NN] = {};
        #pragma unroll 2
        for (int kp = 0; kp < 32; kp++) {
            ull wi1 = ldg2(&g_wih2[(kp * 256 + 64 + c) * 2]);
            ull wh1 = ldg2(&g_whh2[(kp * 256 + 64 + c) * 2]);
            ull wi3 = ldg2(&g_wih2[(kp * 256 + 192 + c) * 2]);
            ull wh3 = ldg2(&g_whh2[(kp * 256 + 192 + c) * 2]);
            #pragma unroll
            for (int r = 0; r < NN; r++) {
                ull aA = ldsm2(&s->A[r][2 * kp]);
                ull aH = ldsm2(&s->hx[r][2 * kp]);
                ffma2(a1[r], aA, wi1);
                ffma2(a1[r], aH, wh1);
                ffma2(a3[r], aA, wi3);
                ffma2(a3[r], aH, wh3);
            }
        }
        float bF = __ldg(&b_ih[64 + c])  + __ldg(&b_hh[64 + c]);
        float bO = __ldg(&b_ih[192 + c]) + __ldg(&b_hh[192 + c]);
        __syncthreads();   // all hx reads complete before overwrite
        #pragma unroll
        for (int r = 0; r < NN; r++) {
            float gf = sigm_f(hsum(a1[r]) + bF);
            float go = sigm_f(hsum(a3[r]) + bO);
            float cc = gf * s->cx[r][c] + ig[r];
            s->cx[r][c] = cc;
            s->hx[r][c] = go * tanh_f(cc);
        }
    }
    __syncthreads();
}

__global__ void __launch_bounds__(BT, 12)
stgnn_kernel(const float* __restrict__ xh,    const float* __restrict__ adj,
             const float* __restrict__ enc_b,
             const float* __restrict__ g1b,   const float* __restrict__ g2b,
             const float* __restrict__ b_ih,  const float* __restrict__ b_hh,
             const float* __restrict__ d1b,   const float* __restrict__ d2b,
             float* __restrict__ out) {
    __shared__ Smem sm;
    Smem* s = &sm;
    const int c = threadIdx.x;     // 0..63
    const int b = blockIdx.x;      // batch element

    // ---- normalized adjacency + zero state ----
    if (c < 49) {
        int i = c / 7, j = c - i * 7;
        s->adjn[c] = (i == j) ? 1.0f : __ldg(&adj[b * 49 + c]);
    }
    #pragma unroll
    for (int r = 0; r < NN; r++) { s->hx[r][c] = 0.f; s->cx[r][c] = 0.f; }
    __syncthreads();
    if (c < NN) {
        float sum = 0.f;
        #pragma unroll
        for (int j = 0; j < NN; j++) sum += s->adjn[c * 7 + j];
        s->deg[c] = rsqrtf(fmaxf(sum, 1.0f));
    }
    __syncthreads();
    if (c < 49) {
        int i = c / 7, j = c - i * 7;
        s->adjn[c] *= s->deg[i] * s->deg[j];
    }
    __syncthreads();

    // ---- history scan ----
    #pragma unroll 1
    for (int t = 0; t < T_; t++) {
        for (int idx = c; idx < NN * 12; idx += BT) {
            int r = idx / 12, k = idx - r * 12;
            float v = 0.f;
            if (k < INV) v = __ldg(&xh[((b * T_ + t) * NN + r) * INV + k]);
            s->xt[r][k] = v;
        }
        __syncthreads();
        cell(s, c, enc_b, g1b, g2b, b_ih, b_hh);
    }

    // ---- pred/stat init from last history step ----
    for (int idx = c; idx < NN * INV; idx += BT) {
        int r = idx / INV, k = idx - r * INV;
        float v = __ldg(&xh[((b * T_ + (T_ - 1)) * NN + r) * INV + k]);
        if (k < DYNV) s->pred[r][k] = v;
        else          s->stat[r][k - DYNV] = v;
    }
    __syncthreads();

    // ---- future rollout ----
    #pragma unroll 1
    for (int f = 0; f < FUT; f++) {
        for (int idx = c; idx < NN * 12; idx += BT) {
            int r = idx / 12, k = idx - r * 12;
            float v = 0.f;
            if (k < DYNV)     v = s->pred[r][k];
            else if (k < INV) v = s->stat[r][k - DYNV];
            s->xt[r][k] = v;
        }
        __syncthreads();
        cell(s, c, enc_b, g1b, g2b, b_ih, b_hh);

        // decoder layer 1: cols 0..31 of A = relu(hx @ d1w + d1b); threads 0..31
        if (c < 32) {
            ull acc[NN] = {};
            #pragma unroll 4
            for (int kp = 0; kp < 32; kp++) {
                ull w = ldg2(&g_d1w2[(kp * 32 + c) * 2]);
                #pragma unroll
                for (int r = 0; r < NN; r++)
                    ffma2(acc[r], ldsm2(&s->hx[r][2 * kp]), w);
            }
            float bb = __ldg(&d1b[c]);
            #pragma unroll
            for (int r = 0; r < NN; r++)
                s->A[r][c] = fmaxf(hsum(acc[r]) + bb, 0.f);
        }
        __syncthreads();

        // decoder layer 2 + residual + clip + output (42 threads)
        if (c < NN * DYNV) {
            int r = c / DYNV, d = c - r * DYNV;
            ull acc = 0;
            float z = 0.f;
            asm("mov.b64 %0, {%1, %1};" : "=l"(acc) : "f"(z));
            #pragma unroll
            for (int kp = 0; kp < 16; kp++)
                ffma2(acc, ldsm2(&s->A[r][2 * kp]), ldg2(&g_d2w2[(kp * 6 + d) * 2]));
            float res = tanh_f(hsum(acc) + __ldg(&d2b[d])) * 0.05f;
            float p = fminf(fmaxf(s->pred[r][d] + res, 0.f), 1.f);
            s->pred[r][d] = p;
            out[((b * FUT + f) * NN + r) * DYNV + d] = p;
        }
        __syncthreads();
    }
}

extern "C" void kernel_launch(void* const* d_in, const int* in_sizes, int n_in,
                              void* d_out, int out_size) {
    const float* xh    = (const float*)d_in[0];
    const float* adj   = (const float*)d_in[1];
    const float* enc_w = (const float*)d_in[2];
    const float* enc_b = (const float*)d_in[3];
    const float* g1w   = (const float*)d_in[4];
    const float* g1b   = (const float*)d_in[5];
    const float* g2w   = (const float*)d_in[6];
    const float* g2b   = (const float*)d_in[7];
    const float* w_ih  = (const float*)d_in[8];
    const float* w_hh  = (const float*)d_in[9];
    const float* b_ih  = (const float*)d_in[10];
    const float* b_hh  = (const float*)d_in[11];
    const float* d1w   = (const float*)d_in[12];
    const float* d1b   = (const float*)d_in[13];
    const float* d2w   = (const float*)d_in[14];
    const float* d2b   = (const float*)d_in[15];
    float* out = (float*)d_out;

    pack_weights<<<(23488 + 255) / 256, 256>>>(w_ih, w_hh, g1w, g2w, enc_w, d1w, d2w);
    stgnn_kernel<<<B_, BT>>>(xh, adj, enc_b, g1b, g2b, b_ih, b_hh, d1b, d2b, out);
}

// round 8
// speedup vs baseline: 1.8025x; 1.1489x over previous
#include <cuda_runtime.h>
#include <math.h>

#define B_    4096
#define T_    24
#define NN    7
#define DYNV  6
#define INV   11
#define H     64
#define FUT   48

#define BT    64            // threads per block, one batch element per block
#define HS    68            // padded row stride (floats)

typedef unsigned long long ull;

// Quad-packed weights: [(kq*C + c)*4 + q] = W[4kq+q][c]
__device__ float g_wih4[16 * 256 * 4];
__device__ float g_whh4[16 * 256 * 4];
__device__ float g_g1w4[16 * 64 * 4];
__device__ float g_g2w4[16 * 64 * 4];
__device__ float g_enc4[3 * 64 * 4];     // k padded 11 -> 12
__device__ float g_d1w4[16 * 32 * 4];
__device__ float g_d2w2[16 * 6 * 2];     // pair-packed (tiny)

__global__ void pack_weights(const float* __restrict__ w_ih, const float* __restrict__ w_hh,
                             const float* __restrict__ g1w,  const float* __restrict__ g2w,
                             const float* __restrict__ enc_w,
                             const float* __restrict__ d1w,  const float* __restrict__ d2w) {
    int i = blockIdx.x * blockDim.x + threadIdx.x;
    if (i < 16384) {
        int q = i & 3, gc = (i >> 2) & 255, kq = i >> 10;
        g_wih4[i] = w_ih[gc * 64 + 4 * kq + q];     // w_ih is [256][64]
        g_whh4[i] = w_hh[gc * 64 + 4 * kq + q];
    } else if (i < 16384 + 4096) {
        int j = i - 16384;
        int q = j & 3, c = (j >> 2) & 63, kq = j >> 8;
        g_g1w4[j] = g1w[(4 * kq + q) * 64 + c];     // g1w is [64][64]
        g_g2w4[j] = g2w[(4 * kq + q) * 64 + c];
    } else if (i < 16384 + 4096 + 768) {
        int j = i - 16384 - 4096;
        int q = j & 3, c = (j >> 2) & 63, kq = j >> 8;
        int k = 4 * kq + q;
        g_enc4[j] = (k < INV) ? enc_w[k * 64 + c] : 0.f;
    } else if (i < 16384 + 4096 + 768 + 2048) {
        int j = i - 16384 - 4096 - 768;
        int q = j & 3, c = (j >> 2) & 31, kq = j >> 7;
        g_d1w4[j] = d1w[(4 * kq + q) * 32 + c];
    } else if (i < 16384 + 4096 + 768 + 2048 + 192) {
        int j = i - (16384 + 4096 + 768 + 2048);
        int kp = j / 12, rr = j - kp * 12, d = rr >> 1, p = rr & 1;
        g_d2w2[j] = d2w[(2 * kp + p) * 6 + d];
    }
}

// ---------- helpers ----------
__device__ __forceinline__ ulonglong2 ldg4(const float* p) {
    return __ldg(reinterpret_cast<const ulonglong2*>(p));
}
__device__ __forceinline__ ulonglong2 lds4(const float* p) {
    return *reinterpret_cast<const ulonglong2*>(p);
}
__device__ __forceinline__ ull ldsm2(const float* p) { return *reinterpret_cast<const ull*>(p); }
__device__ __forceinline__ ull ldg2(const float* p)  { return __ldg(reinterpret_cast<const ull*>(p)); }
__device__ __forceinline__ void ffma2(ull& d, ull a, ull b) {
    asm("fma.rn.f32x2 %0, %1, %2, %3;" : "=l"(d) : "l"(a), "l"(b), "l"(d));
}
__device__ __forceinline__ float hsum(ull v) {
    float2 f = *reinterpret_cast<float2*>(&v);
    return f.x + f.y;
}
__device__ __forceinline__ float sigm_f(float x) { return __fdividef(1.f, 1.f + __expf(-x)); }
__device__ __forceinline__ float tanh_f(float x) {
    float e = __expf(2.f * x);
    return 1.f - __fdividef(2.f, e + 1.f);
}

struct __align__(16) Smem {
    float xt[NN][12];
    float A[NN][HS];
    float Bv[NN][HS];
    float hx[NN][HS];
    float cx[NN][HS];
    float adjn[49];
    float deg[8];
    float pred[NN][DYNV];
    float stat[NN][8];
};

// GCN layer fused: out[i][c] = relu( sum_j adjn[i][j] * (in @ W)[j][c] + bias[c] )
// GEMM intermediate for column c stays in registers of thread c.
__device__ __forceinline__ void gcn_fused(const Smem* s, const float (*in)[HS],
                                          const float* __restrict__ w4,
                                          float (*out)[HS],
                                          const float* __restrict__ bias, int c) {
    ull acc[NN] = {};
    #pragma unroll
    for (int kq = 0; kq < 16; kq++) {
        ulonglong2 w = ldg4(&w4[(kq * 64 + c) * 4]);
        #pragma unroll
        for (int r = 0; r < NN; r++) {
            ulonglong2 a = lds4(&in[r][4 * kq]);
            ffma2(acc[r], a.x, w.x);
            ffma2(acc[r], a.y, w.y);
        }
    }
    float bv[NN];
    #pragma unroll
    for (int r = 0; r < NN; r++) bv[r] = hsum(acc[r]);
    float bb = __ldg(&bias[c]);
    #pragma unroll
    for (int i = 0; i < NN; i++) {
        float a = bb;
        #pragma unroll
        for (int j = 0; j < NN; j++)
            a = fmaf(s->adjn[i * 7 + j], bv[j], a);
        out[i][c] = fmaxf(a, 0.f);
    }
}

// One cell step. xt filled+synced on entry; hx/cx updated+synced on exit.
__device__ __forceinline__ void cell(Smem* s, int c,
        const float* __restrict__ enc_b,
        const float* __restrict__ g1b, const float* __restrict__ g2b,
        const float* __restrict__ b_ih, const float* __restrict__ b_hh) {
    // encoder -> A
    {
        ull acc[NN] = {};
        #pragma unroll
        for (int kq = 0; kq < 3; kq++) {
            ulonglong2 w = ldg4(&g_enc4[(kq * 64 + c) * 4]);
            #pragma unroll
            for (int r = 0; r < NN; r++) {
                ulonglong2 a = lds4(&s->xt[r][4 * kq]);
                ffma2(acc[r], a.x, w.x);
                ffma2(acc[r], a.y, w.y);
            }
        }
        float bb = __ldg(&enc_b[c]);
        #pragma unroll
        for (int r = 0; r < NN; r++)
            s->A[r][c] = fmaxf(hsum(acc[r]) + bb, 0.f);
    }
    __syncthreads();
    gcn_fused(s, s->A, g_g1w4, s->Bv, g1b, c);      // A -> Bv
    __syncthreads();
    gcn_fused(s, s->Bv, g_g2w4, s->A, g2b, c);      // Bv -> A
    __syncthreads();

    // LSTM gates, SINGLE pass: thread c owns cols {c, c+64, c+128, c+192}.
    // Each activation LDS feeds all 4 gates.
    {
        ull a0[NN] = {}, a1[NN] = {}, a2[NN] = {}, a3[NN] = {};
        #pragma unroll 8
        for (int kq = 0; kq < 16; kq++) {
            ulonglong2 wi0 = ldg4(&g_wih4[(kq * 256 + c) * 4]);
            ulonglong2 wh0 = ldg4(&g_whh4[(kq * 256 + c) * 4]);
            ulonglong2 wi1 = ldg4(&g_wih4[(kq * 256 + 64 + c) * 4]);
            ulonglong2 wh1 = ldg4(&g_whh4[(kq * 256 + 64 + c) * 4]);
            ulonglong2 wi2 = ldg4(&g_wih4[(kq * 256 + 128 + c) * 4]);
            ulonglong2 wh2 = ldg4(&g_whh4[(kq * 256 + 128 + c) * 4]);
            ulonglong2 wi3 = ldg4(&g_wih4[(kq * 256 + 192 + c) * 4]);
            ulonglong2 wh3 = ldg4(&g_whh4[(kq * 256 + 192 + c) * 4]);
            #pragma unroll
            for (int r = 0; r < NN; r++) {
                ulonglong2 aA = lds4(&s->A[r][4 * kq]);
                ulonglong2 aH = lds4(&s->hx[r][4 * kq]);
                ffma2(a0[r], aA.x, wi0.x); ffma2(a0[r], aA.y, wi0.y);
                ffma2(a0[r], aH.x, wh0.x); ffma2(a0[r], aH.y, wh0.y);
                ffma2(a1[r], aA.x, wi1.x); ffma2(a1[r], aA.y, wi1.y);
                ffma2(a1[r], aH.x, wh1.x); ffma2(a1[r], aH.y, wh1.y);
                ffma2(a2[r], aA.x, wi2.x); ffma2(a2[r], aA.y, wi2.y);
                ffma2(a2[r], aH.x, wh2.x); ffma2(a2[r], aH.y, wh2.y);
                ffma2(a3[r], aA.x, wi3.x); ffma2(a3[r], aA.y, wi3.y);
                ffma2(a3[r], aH.x, wh3.x); ffma2(a3[r], aH.y, wh3.y);
            }
        }
        float bI = __ldg(&b_ih[c])       + __ldg(&b_hh[c]);
        float bF = __ldg(&b_ih[64 + c])  + __ldg(&b_hh[64 + c]);
        float bG = __ldg(&b_ih[128 + c]) + __ldg(&b_hh[128 + c]);
        float bO = __ldg(&b_ih[192 + c]) + __ldg(&b_hh[192 + c]);
        __syncthreads();   // all A/hx reads complete before hx overwrite
        #pragma unroll
        for (int r = 0; r < NN; r++) {
            float gi = sigm_f(hsum(a0[r]) + bI);
            float gf = sigm_f(hsum(a1[r]) + bF);
            float gg = tanh_f(hsum(a2[r]) + bG);
            float go = sigm_f(hsum(a3[r]) + bO);
            float cc = gf * s->cx[r][c] + gi * gg;
            s->cx[r][c] = cc;
            s->hx[r][c] = go * tanh_f(cc);
        }
    }
    __syncthreads();
}

__global__ void __launch_bounds__(BT, 8)
stgnn_kernel(const float* __restrict__ xh,    const float* __restrict__ adj,
             const float* __restrict__ enc_b,
             const float* __restrict__ g1b,   const float* __restrict__ g2b,
             const float* __restrict__ b_ih,  const float* __restrict__ b_hh,
             const float* __restrict__ d1b,   const float* __restrict__ d2b,
             float* __restrict__ out) {
    __shared__ Smem sm;
    Smem* s = &sm;
    const int c = threadIdx.x;     // 0..63
    const int b = blockIdx.x;      // batch element

    // ---- normalized adjacency + zero state ----
    if (c < 49) {
        int i = c / 7, j = c - i * 7;
        s->adjn[c] = (i == j) ? 1.0f : __ldg(&adj[b * 49 + c]);
    }
    #pragma unroll
    for (int r = 0; r < NN; r++) { s->hx[r][c] = 0.f; s->cx[r][c] = 0.f; }
    __syncthreads();
    if (c < NN) {
        float sum = 0.f;
        #pragma unroll
        for (int j = 0; j < NN; j++) sum += s->adjn[c * 7 + j];
        s->deg[c] = rsqrtf(fmaxf(sum, 1.0f));
    }
    __syncthreads();
    if (c < 49) {
        int i = c / 7, j = c - i * 7;
        s->adjn[c] *= s->deg[i] * s->deg[j];
    }
    __syncthreads();

    // ---- history scan ----
    #pragma unroll 1
    for (int t = 0; t < T_; t++) {
        for (int idx = c; idx < NN * 12; idx += BT) {
            int r = idx / 12, k = idx - r * 12;
            float v = 0.f;
            if (k < INV) v = __ldg(&xh[((b * T_ + t) * NN + r) * INV + k]);
            s->xt[r][k] = v;
        }
        __syncthreads();
        cell(s, c, enc_b, g1b, g2b, b_ih, b_hh);
    }

    // ---- pred/stat init from last history step ----
    for (int idx = c; idx < NN * INV; idx += BT) {
        int r = idx / INV, k = idx - r * INV;
        float v = __ldg(&xh[((b * T_ + (T_ - 1)) * NN + r) * INV + k]);
        if (k < DYNV) s->pred[r][k] = v;
        else          s->stat[r][k - DYNV] = v;
    }
    __syncthreads();

    // ---- future rollout ----
    #pragma unroll 1
    for (int f = 0; f < FUT; f++) {
        for (int idx = c; idx < NN * 12; idx += BT) {
            int r = idx / 12, k = idx - r * 12;
            float v = 0.f;
            if (k < DYNV)     v = s->pred[r][k];
            else if (k < INV) v = s->stat[r][k - DYNV];
            s->xt[r][k] = v;
        }
        __syncthreads();
        cell(s, c, enc_b, g1b, g2b, b_ih, b_hh);

        // decoder layer 1: Bv[:, :32] = relu(hx @ d1w + d1b); threads 0..31
        if (c < 32) {
            ull acc[NN] = {};
            #pragma unroll
            for (int kq = 0; kq < 16; kq++) {
                ulonglong2 w = ldg4(&g_d1w4[(kq * 32 + c) * 4]);
                #pragma unroll
                for (int r = 0; r < NN; r++) {
                    ulonglong2 a = lds4(&s->hx[r][4 * kq]);
                    ffma2(acc[r], a.x, w.x);
                    ffma2(acc[r], a.y, w.y);
                }
            }
            float bb = __ldg(&d1b[c]);
            #pragma unroll
            for (int r = 0; r < NN; r++)
                s->Bv[r][c] = fmaxf(hsum(acc[r]) + bb, 0.f);
        }
        __syncthreads();

        // decoder layer 2 + residual + clip + output (42 threads)
        if (c < NN * DYNV) {
            int r = c / DYNV, d = c - r * DYNV;
            ull acc = 0;
            float z = 0.f;
            asm("mov.b64 %0, {%1, %1};" : "=l"(acc) : "f"(z));
            #pragma unroll
            for (int kp = 0; kp < 16; kp++)
                ffma2(acc, ldsm2(&s->Bv[r][2 * kp]), ldg2(&g_d2w2[(kp * 6 + d) * 2]));
            float res = tanh_f(hsum(acc) + __ldg(&d2b[d])) * 0.05f;
            float p = fminf(fmaxf(s->pred[r][d] + res, 0.f), 1.f);
            s->pred[r][d] = p;
            out[((b * FUT + f) * NN + r) * DYNV + d] = p;
        }
        __syncthreads();
    }
}

extern "C" void kernel_launch(void* const* d_in, const int* in_sizes, int n_in,
                              void* d_out, int out_size) {
    const float* xh    = (const float*)d_in[0];
    const float* adj   = (const float*)d_in[1];
    const float* enc_w = (const float*)d_in[2];
    const float* enc_b = (const float*)d_in[3];
    const float* g1w   = (const float*)d_in[4];
    const float* g1b   = (const float*)d_in[5];
    const float* g2w   = (const float*)d_in[6];
    const float* g2b   = (const float*)d_in[7];
    const float* w_ih  = (const float*)d_in[8];
    const float* w_hh  = (const float*)d_in[9];
    const float* b_ih  = (const float*)d_in[10];
    const float* b_hh  = (const float*)d_in[11];
    const float* d1w   = (const float*)d_in[12];
    const float* d1b   = (const float*)d_in[13];
    const float* d2w   = (const float*)d_in[14];
    const float* d2b   = (const float*)d_in[15];
    float* out = (float*)d_out;

    pack_weights<<<(23488 + 255) / 256, 256>>>(w_ih, w_hh, g1w, g2w, enc_w, d1w, d2w);
    stgnn_kernel<<<B_, BT>>>(xh, adj, enc_b, g1b, g2b, b_ih, b_hh, d1b, d2b, out);
}